// round 14
// baseline (speedup 1.0000x reference)
#include <cuda_runtime.h>
#include <cuda_fp16.h>
#include <cstdint>

// DigitCaps1D dynamic routing. B=64, N=8192, Di=8, O=10, Do=16, 3 rounds.
//
// Round 0: c = 0.1 exactly. Computes u_hat (f32), accumulates s0, stores
//          u_hat as fp16 for the routed rounds. o-axis split across two
//          kernel instantiations (o0..5 / o6..9) to halve W register load.
// Rounds 1-2: read fp16 u_hat; NO W access, NO GEMM. logits vs v0 / (v0+v1).

#define B    64
#define NN   8192
#define DI   8
#define OO   10
#define DO   16
#define OD   160
// pass0 tiling
#define TILE_N 8
#define NBLK   1024         // NN / TILE_N
#define NSLICE 16
#define KPER   64           // NBLK / NSLICE
// routed tiling
#define TILE_R 32
#define RNB    256          // NN / TILE_R

typedef unsigned long long ull;

__device__ float    g_part [NBLK * B * OD];    // round-0 partials (42 MB)
__device__ float    g_part2[NSLICE * B * OD];
__device__ float    g_sum  [B * OD];           // routed-round sums
__device__ float    g_partr[B * RNB * OD];     // routed partials (10.5 MB)
__device__ float    g_vt   [B * DO * OO];      // v_eff f32, [b][d][o]
__device__ uint2    g_uhA  [NN * B * DO];      // u_hat fp16, o=0..3  (67 MB)
__device__ unsigned g_uhB1 [NN * B * DO];      // u_hat fp16, o=4,5   (34 MB)
__device__ unsigned g_uhB2 [NN * B * DO];      // u_hat fp16, o=6,7   (34 MB)
__device__ unsigned g_uhC  [NN * B * DO];      // u_hat fp16, o=8,9   (34 MB)

// ---- packed f32x2 helpers (ptxas won't emit FFMA2 from C++) ----
__device__ __forceinline__ ull fma2(ull a, ull b, ull c) {
    ull d; asm("fma.rn.f32x2 %0,%1,%2,%3;" : "=l"(d) : "l"(a), "l"(b), "l"(c)); return d;
}
__device__ __forceinline__ ull mul2(ull a, ull b) {
    ull d; asm("mul.rn.f32x2 %0,%1,%2;" : "=l"(d) : "l"(a), "l"(b)); return d;
}
__device__ __forceinline__ void unpack2(ull v, float& lo, float& hi) {
    asm("mov.b64 {%0,%1},%2;" : "=f"(lo), "=f"(hi) : "l"(v));
}
__device__ __forceinline__ unsigned hbits(__half2 h) {
    return *reinterpret_cast<unsigned*>(&h);
}
__device__ __forceinline__ __half2 bith(unsigned u) {
    return *reinterpret_cast<__half2*>(&u);
}

// ---------- Round 0: GEMM + 0.1-sum + u_hat fp16 store, o-chunked ----------
// OB = first o of chunk, ON = number of o's (6 or 4; ON even).
template<int OB, int ON>
__global__ void __launch_bounds__(128)
pass0_kernel(const float* __restrict__ x, const float* __restrict__ W)
{
    __shared__ float s_sm[B * DO * ON];   // [b][d][k], per-lane-owned cells

    const int blk  = blockIdx.x;
    const int n0   = blk * TILE_N;
    const int tid  = threadIdx.x;
    const int lane = tid & 31;
    const int warp = tid >> 5;
    const int half = lane >> 4;
    const int hw   = warp * 2 + half;     // 0..7 -> owns b = hw*8..hw*8+7
    const int d    = lane & 15;

    #pragma unroll
    for (int j = 0; j < 8; ++j) {
        float2* sc2 = reinterpret_cast<float2*>(&s_sm[((hw * 8 + j) * DO + d) * ON]);
        #pragma unroll
        for (int k = 0; k < ON / 2; ++k) sc2[k] = make_float2(0.f, 0.f);
    }

    const ulonglong2* x2 = reinterpret_cast<const ulonglong2*>(x);
    const ulonglong2* W2 = reinterpret_cast<const ulonglong2*>(W);

    for (int nn = 0; nn < TILE_N; ++nn) {
        const int n = n0 + nn;

        ulonglong2 wA[ON], wB[ON];        // W[n, OB+k, d, 0..7], reused 8 b's
        #pragma unroll
        for (int k = 0; k < ON; ++k) {
            const int base = ((n * OO + OB + k) * DO + d) * 2;
            wA[k] = W2[base];
            wB[k] = W2[base + 1];
        }

        #pragma unroll
        for (int j = 0; j < 8; ++j) {
            const int b = hw * 8 + j;
            const ulonglong2 xa = x2[(b * NN + n) * 2];
            const ulonglong2 xb = x2[(b * NN + n) * 2 + 1];

            float u[ON];
            #pragma unroll
            for (int k = 0; k < ON; ++k) {
                ull a = mul2(wA[k].x, xa.x);
                a = fma2(wA[k].y, xa.y, a);
                a = fma2(wB[k].x, xb.x, a);
                a = fma2(wB[k].y, xb.y, a);
                float lo, hi; unpack2(a, lo, hi);
                u[k] = lo + hi;
            }

            // store u_hat fp16: layout [n][b][d], coalesced across d
            const int ui = (n * B + b) * DO + d;
            if (OB == 0) {
                g_uhA[ui]  = make_uint2(hbits(__floats2half2_rn(u[0], u[1])),
                                        hbits(__floats2half2_rn(u[2], u[3])));
                g_uhB1[ui] = hbits(__floats2half2_rn(u[4], u[5]));
            } else {
                g_uhB2[ui] = hbits(__floats2half2_rn(u[0], u[1]));
                g_uhC[ui]  = hbits(__floats2half2_rn(u[2], u[3]));
            }

            float2* sc2 = reinterpret_cast<float2*>(&s_sm[(b * DO + d) * ON]);
            #pragma unroll
            for (int k = 0; k < ON / 2; ++k) {
                float2 sv = sc2[k];
                sv.x += u[2 * k]; sv.y += u[2 * k + 1];
                sc2[k] = sv;
            }
        }
    }

    float* gp = g_part + blk * (B * OD);
    #pragma unroll
    for (int j = 0; j < 8; ++j) {
        const int b = hw * 8 + j;
        #pragma unroll
        for (int k = 0; k < ON; ++k)
            gp[b * OD + (OB + k) * DO + d] = s_sm[(b * DO + d) * ON + k];
    }
}

// ---------------- Rounds 1-2: routed pass, fp16 u_hat, no W ----------------
// grid = 8 b-groups x RNB n-chunks = 2048 blocks. Half-warp owns ONE b.
__global__ void __launch_bounds__(128)
routed_kernel()
{
    const int bg   = blockIdx.x & 7;
    const int nb   = blockIdx.x >> 3;
    const int tid  = threadIdx.x;
    const int lane = tid & 31;
    const int warp = tid >> 5;
    const int half = lane >> 4;
    const int d    = lane & 15;
    const int b    = bg * 8 + warp * 2 + half;

    // hoist v_eff[b][d][0..9]; pack logit-side copy to half2
    float vf[OO];
    #pragma unroll
    for (int o = 0; o < OO; ++o) vf[o] = g_vt[(b * DO + d) * OO + o];
    unsigned vh[5];
    #pragma unroll
    for (int k = 0; k < 5; ++k)
        vh[k] = hbits(__floats2half2_rn(vf[2 * k], vf[2 * k + 1]));

    float acc[OO];
    #pragma unroll
    for (int o = 0; o < OO; ++o) acc[o] = 0.f;

    const int n0 = nb * TILE_R;
    #pragma unroll 2
    for (int nn = 0; nn < TILE_R; ++nn) {
        const int ui = ((n0 + nn) * B + b) * DO + d;
        const uint2 qa = g_uhA[ui];
        unsigned uh[5] = { qa.x, qa.y, g_uhB1[ui], g_uhB2[ui], g_uhC[ui] };

        // logit partials in fp16: p = u * v
        unsigned ph[5];
        #pragma unroll
        for (int k = 0; k < 5; ++k)
            ph[k] = hbits(__hmul2(bith(uh[k]), bith(vh[k])));
        // 16-lane butterfly (halves are different b's; xor<16 stays in-half)
        #pragma unroll
        for (int s = 1; s < 16; s <<= 1) {
            #pragma unroll
            for (int k = 0; k < 5; ++k) {
                const unsigned t = __shfl_xor_sync(0xffffffffu, ph[k], s, 32);
                ph[k] = hbits(__hadd2(bith(ph[k]), bith(t)));
            }
        }

        float p[OO], e[OO];
        #pragma unroll
        for (int k = 0; k < 5; ++k) {
            const float2 f = __half22float2(bith(ph[k]));
            p[2 * k] = f.x; p[2 * k + 1] = f.y;
        }
        // softmax over o; no max-subtract (|p| small); deg-3 Taylor exp
        #pragma unroll
        for (int o = 0; o < OO; ++o) {
            float t = fmaf(p[o], 1.6666667e-1f, 0.5f);
            t = fmaf(t, p[o], 1.0f);
            t = fmaf(t, p[o], 1.0f);
            e[o] = t;
        }
        const float sum = ((e[0] + e[1]) + (e[2] + e[3]))
                        + ((e[4] + e[5]) + (e[6] + e[7])) + (e[8] + e[9]);
        const float inv = __fdividef(1.f, sum);
        #pragma unroll
        for (int k = 0; k < 5; ++k) {
            const float2 uf = __half22float2(bith(uh[k]));
            acc[2 * k]     = fmaf(e[2 * k] * inv,     uf.x, acc[2 * k]);
            acc[2 * k + 1] = fmaf(e[2 * k + 1] * inv, uf.y, acc[2 * k + 1]);
        }
    }

    float* gp = &g_partr[(b * RNB + nb) * OD];
    #pragma unroll
    for (int o = 0; o < OO; ++o)
        gp[o * DO + d] = acc[o];
}

// ---------------- reductions ----------------
__global__ void __launch_bounds__(160)
reduce1_kernel()   // round-0 stage 1: 64 block-partials per (b, slice)
{
    const int bi = blockIdx.x;
    const int b  = bi >> 4;
    const int s  = bi & 15;
    const int od = threadIdx.x;

    const float* gp = g_part + (s * KPER) * (B * OD) + b * OD + od;
    float acc = 0.f;
    #pragma unroll 8
    for (int k = 0; k < KPER; ++k)
        acc += gp[k * (B * OD)];
    g_part2[(b * NSLICE + s) * OD + od] = acc;
}

__global__ void __launch_bounds__(160)
reduce_r_kernel()  // routed rounds: sum RNB chunk-partials per b
{
    const int b  = blockIdx.x;
    const int od = threadIdx.x;
    float a = 0.f;
    #pragma unroll 8
    for (int k = 0; k < RNB; ++k)
        a += g_partr[(b * RNB + k) * OD + od];
    g_sum[b * OD + od] = a;
}

// squash (norm over the O axis, faithful to the reference)
__global__ void __launch_bounds__(160)
squash_kernel(float* __restrict__ out, float prescale, int mode)
{
    __shared__ float sm[OD];
    const int b  = blockIdx.x;
    const int od = threadIdx.x;

    float acc = 0.f;
    if (mode == 0) {
        #pragma unroll
        for (int s = 0; s < NSLICE; ++s)
            acc += g_part2[(b * NSLICE + s) * OD + od];
    } else {
        acc = g_sum[b * OD + od];
    }
    acc *= prescale;
    sm[od] = acc;
    __syncthreads();

    const int d = od & 15;
    const int o = od >> 4;
    float norm = 0.f;
    #pragma unroll
    for (int oo = 0; oo < OO; ++oo) {
        const float z = sm[oo * DO + d];
        norm = fmaf(z, z, norm);
    }
    const float scale = norm / (1.f + norm) * rsqrtf(norm + 1e-9f);
    const float v = scale * acc;

    if (mode == 0)      g_vt[(b * DO + d) * OO + o] = v;      // v0
    else if (mode == 1) g_vt[(b * DO + d) * OO + o] += v;     // v0 + v1
    else                out[b * OD + od] = v;                 // final v2
}

extern "C" void kernel_launch(void* const* d_in, const int* in_sizes, int n_in,
                              void* d_out, int out_size)
{
    const float* x = (const float*)d_in[0];
    const float* W = (const float*)d_in[1];
    if (in_sizes[0] != B * NN * DI) {     // defensive input-order check
        x = (const float*)d_in[1];
        W = (const float*)d_in[0];
    }
    float* out = (float*)d_out;

    // Round 0: GEMM + c=0.1 sum + u_hat fp16 store (o-chunked)
    pass0_kernel<0, 6><<<NBLK, 128>>>(x, W);
    pass0_kernel<6, 4><<<NBLK, 128>>>(x, W);
    reduce1_kernel<<<B * NSLICE, 160>>>();
    squash_kernel<<<B, 160>>>(out, 0.1f, 0);
    // Round 1: logits vs v0
    routed_kernel<<<8 * RNB, 128>>>();
    reduce_r_kernel<<<B, 160>>>();
    squash_kernel<<<B, 160>>>(out, 1.0f, 1);
    // Round 2: logits vs v0+v1, final output
    routed_kernel<<<8 * RNB, 128>>>();
    reduce_r_kernel<<<B, 160>>>();
    squash_kernel<<<B, 160>>>(out, 1.0f, 2);
}

// round 15
// speedup vs baseline: 1.7201x; 1.7201x over previous
#include <cuda_runtime.h>
#include <cuda_fp16.h>
#include <cstdint>

// DigitCaps1D dynamic routing. B=64, N=8192, Di=8, O=10, Do=16, 3 rounds.
//
// Round 0: c = 0.1 exactly. Computes u_hat (f32), accumulates s0, AND stores
//          u_hat as fp16 (168 MB) for the routed rounds.
// Rounds 1-2: read fp16 u_hat; NO W access, NO GEMM. logits vs v0 / (v0+v1).
// Only v_eff ([64][16][10] f32) carried between rounds.

#define B    64
#define NN   8192
#define DI   8
#define OO   10
#define DO   16
#define OD   160
// pass0 tiling (R7-proven shape)
#define TILE_N 8
#define NBLK   1024         // NN / TILE_N
#define NSLICE 16
#define KPER   64           // NBLK / NSLICE
// routed tiling
#define TILE_R 64
#define RNB    128          // NN / TILE_R

typedef unsigned long long ull;

__device__ float    g_part [NBLK * B * OD];    // round-0 partials (42 MB)
__device__ float    g_part2[NSLICE * B * OD];
__device__ float    g_partr[B * RNB * OD];     // routed partials (5.2 MB)
__device__ float    g_vt   [B * DO * OO];      // v_eff f32, [b][d][o]
__device__ uint2    g_uhA  [NN * B * DO];      // u_hat fp16, o=0..3   (67 MB)
__device__ uint2    g_uhB  [NN * B * DO];      // u_hat fp16, o=4..7   (67 MB)
__device__ unsigned g_uhC  [NN * B * DO];      // u_hat fp16, o=8..9   (34 MB)

// ---- packed f32x2 helpers (ptxas won't emit FFMA2 from C++) ----
__device__ __forceinline__ ull fma2(ull a, ull b, ull c) {
    ull d; asm("fma.rn.f32x2 %0,%1,%2,%3;" : "=l"(d) : "l"(a), "l"(b), "l"(c)); return d;
}
__device__ __forceinline__ ull mul2(ull a, ull b) {
    ull d; asm("mul.rn.f32x2 %0,%1,%2;" : "=l"(d) : "l"(a), "l"(b)); return d;
}
__device__ __forceinline__ void unpack2(ull v, float& lo, float& hi) {
    asm("mov.b64 {%0,%1},%2;" : "=f"(lo), "=f"(hi) : "l"(v));
}
__device__ __forceinline__ unsigned hbits(__half2 h) {
    return *reinterpret_cast<unsigned*>(&h);
}
__device__ __forceinline__ __half2 bith(unsigned u) {
    return *reinterpret_cast<__half2*>(&u);
}

// ---------------- Round 0: GEMM + 0.1-sum + u_hat fp16 store ----------------
__global__ void __launch_bounds__(128)
pass0_kernel(const float* __restrict__ x, const float* __restrict__ W)
{
    __shared__ float s_sm[B * DO * OO];   // [b][d][o], per-lane-owned cells

    const int blk  = blockIdx.x;
    const int n0   = blk * TILE_N;
    const int tid  = threadIdx.x;
    const int lane = tid & 31;
    const int warp = tid >> 5;
    const int half = lane >> 4;
    const int hw   = warp * 2 + half;     // 0..7 -> owns b = hw*8..hw*8+7
    const int d    = lane & 15;

    #pragma unroll
    for (int j = 0; j < 8; ++j) {
        float2* sc2 = reinterpret_cast<float2*>(&s_sm[((hw * 8 + j) * DO + d) * OO]);
        #pragma unroll
        for (int k = 0; k < 5; ++k) sc2[k] = make_float2(0.f, 0.f);
    }

    const ulonglong2* x2 = reinterpret_cast<const ulonglong2*>(x);
    const ulonglong2* W2 = reinterpret_cast<const ulonglong2*>(W);

    for (int nn = 0; nn < TILE_N; ++nn) {
        const int n = n0 + nn;

        ulonglong2 wA[OO], wB[OO];        // W[n, o, d, 0..7], reused for 8 b's
        #pragma unroll
        for (int o = 0; o < OO; ++o) {
            const int base = ((n * OO + o) * DO + d) * 2;
            wA[o] = W2[base];
            wB[o] = W2[base + 1];
        }

        #pragma unroll
        for (int j = 0; j < 8; ++j) {
            const int b = hw * 8 + j;
            const ulonglong2 xa = x2[(b * NN + n) * 2];
            const ulonglong2 xb = x2[(b * NN + n) * 2 + 1];

            float u[OO];
            #pragma unroll
            for (int o = 0; o < OO; ++o) {
                ull a = mul2(wA[o].x, xa.x);
                a = fma2(wA[o].y, xa.y, a);
                a = fma2(wB[o].x, xb.x, a);
                a = fma2(wB[o].y, xb.y, a);
                float lo, hi; unpack2(a, lo, hi);
                u[o] = lo + hi;
            }

            // store u_hat fp16: layout [n][b][d], coalesced across d
            const int ui = (n * B + b) * DO + d;
            g_uhA[ui] = make_uint2(hbits(__floats2half2_rn(u[0], u[1])),
                                   hbits(__floats2half2_rn(u[2], u[3])));
            g_uhB[ui] = make_uint2(hbits(__floats2half2_rn(u[4], u[5])),
                                   hbits(__floats2half2_rn(u[6], u[7])));
            g_uhC[ui] = hbits(__floats2half2_rn(u[8], u[9]));

            float2* sc2 = reinterpret_cast<float2*>(&s_sm[(b * DO + d) * OO]);
            #pragma unroll
            for (int k = 0; k < 5; ++k) {
                float2 sv = sc2[k];
                sv.x += u[2 * k]; sv.y += u[2 * k + 1];
                sc2[k] = sv;
            }
        }
    }

    float* gp = g_part + blk * (B * OD);
    #pragma unroll
    for (int j = 0; j < 8; ++j) {
        const int b = hw * 8 + j;
        #pragma unroll
        for (int o = 0; o < OO; ++o)
            gp[b * OD + o * DO + d] = s_sm[(b * DO + d) * OO + o];
    }
}

// ---------------- Rounds 1-2: routed pass, fp16 u_hat, no W ----------------
// grid = 8 b-groups x RNB n-chunks = 1024 blocks. Half-warp owns ONE b.
// s-accumulator in registers; no shared memory in the body.
__global__ void __launch_bounds__(128)
routed_kernel()
{
    const int bg   = blockIdx.x & 7;
    const int nb   = blockIdx.x >> 3;
    const int tid  = threadIdx.x;
    const int lane = tid & 31;
    const int warp = tid >> 5;
    const int half = lane >> 4;
    const int d    = lane & 15;
    const int b    = bg * 8 + warp * 2 + half;

    // hoist v_eff[b][d][0..9]; pack logit-side copy to half2
    float vf[OO];
    #pragma unroll
    for (int o = 0; o < OO; ++o) vf[o] = g_vt[(b * DO + d) * OO + o];
    unsigned vh[5];
    #pragma unroll
    for (int k = 0; k < 5; ++k)
        vh[k] = hbits(__floats2half2_rn(vf[2 * k], vf[2 * k + 1]));

    float acc[OO];
    #pragma unroll
    for (int o = 0; o < OO; ++o) acc[o] = 0.f;

    const int n0 = nb * TILE_R;
    #pragma unroll 2
    for (int nn = 0; nn < TILE_R; ++nn) {
        const int ui = ((n0 + nn) * B + b) * DO + d;
        const uint2 qa = g_uhA[ui];
        const uint2 qb = g_uhB[ui];
        const unsigned qc = g_uhC[ui];
        unsigned uh[5] = { qa.x, qa.y, qb.x, qb.y, qc };

        // logit partials in fp16: p = u * v
        unsigned ph[5];
        #pragma unroll
        for (int k = 0; k < 5; ++k)
            ph[k] = hbits(__hmul2(bith(uh[k]), bith(vh[k])));
        // 16-lane butterfly (halves are different b's; xor<16 stays in-half)
        #pragma unroll
        for (int s = 1; s < 16; s <<= 1) {
            #pragma unroll
            for (int k = 0; k < 5; ++k) {
                const unsigned t = __shfl_xor_sync(0xffffffffu, ph[k], s, 32);
                ph[k] = hbits(__hadd2(bith(ph[k]), bith(t)));
            }
        }

        float p[OO], e[OO];
        #pragma unroll
        for (int k = 0; k < 5; ++k) {
            const float2 f = __half22float2(bith(ph[k]));
            p[2 * k] = f.x; p[2 * k + 1] = f.y;
        }
        // softmax over o; no max-subtract (|p| small); deg-3 Taylor exp
        #pragma unroll
        for (int o = 0; o < OO; ++o) {
            float t = fmaf(p[o], 1.6666667e-1f, 0.5f);
            t = fmaf(t, p[o], 1.0f);
            t = fmaf(t, p[o], 1.0f);
            e[o] = t;
        }
        const float sum = ((e[0] + e[1]) + (e[2] + e[3]))
                        + ((e[4] + e[5]) + (e[6] + e[7])) + (e[8] + e[9]);
        const float inv = __fdividef(1.f, sum);
        #pragma unroll
        for (int k = 0; k < 5; ++k) {
            const float2 uf = __half22float2(bith(uh[k]));
            acc[2 * k]     = fmaf(e[2 * k] * inv,     uf.x, acc[2 * k]);
            acc[2 * k + 1] = fmaf(e[2 * k + 1] * inv, uf.y, acc[2 * k + 1]);
        }
    }

    float* gp = &g_partr[(b * RNB + nb) * OD];
    #pragma unroll
    for (int o = 0; o < OO; ++o)
        gp[o * DO + d] = acc[o];
}

// ---------------- reductions ----------------
__global__ void __launch_bounds__(160)
reduce1_kernel()   // round-0 stage 1: 64 block-partials per (b, slice)
{
    const int bi = blockIdx.x;
    const int b  = bi >> 4;
    const int s  = bi & 15;
    const int od = threadIdx.x;

    const float* gp = g_part + (s * KPER) * (B * OD) + b * OD + od;
    float acc = 0.f;
    #pragma unroll 8
    for (int k = 0; k < KPER; ++k)
        acc += gp[k * (B * OD)];
    g_part2[(b * NSLICE + s) * OD + od] = acc;
}

// squash: sums partials itself (mode 0: 16 stage-1 slices; modes 1/2: all
// RNB routed chunk-partials), then squashes (norm over the O axis, faithful
// to the reference), updates g_vt / writes output. grid = 64.
__global__ void __launch_bounds__(160)
squash_kernel(float* __restrict__ out, float prescale, int mode)
{
    __shared__ float sm[OD];
    const int b  = blockIdx.x;
    const int od = threadIdx.x;

    float acc = 0.f;
    if (mode == 0) {
        #pragma unroll
        for (int s = 0; s < NSLICE; ++s)
            acc += g_part2[(b * NSLICE + s) * OD + od];
    } else {
        const float* gp = g_partr + b * (RNB * OD) + od;
        #pragma unroll 8
        for (int k = 0; k < RNB; ++k)
            acc += gp[k * OD];
    }
    acc *= prescale;
    sm[od] = acc;
    __syncthreads();

    const int d = od & 15;
    const int o = od >> 4;
    float norm = 0.f;
    #pragma unroll
    for (int oo = 0; oo < OO; ++oo) {
        const float z = sm[oo * DO + d];
        norm = fmaf(z, z, norm);
    }
    const float scale = norm / (1.f + norm) * rsqrtf(norm + 1e-9f);
    const float v = scale * acc;

    if (mode == 0)      g_vt[(b * DO + d) * OO + o] = v;      // v0
    else if (mode == 1) g_vt[(b * DO + d) * OO + o] += v;     // v0 + v1
    else                out[b * OD + od] = v;                 // final v2
}

extern "C" void kernel_launch(void* const* d_in, const int* in_sizes, int n_in,
                              void* d_out, int out_size)
{
    const float* x = (const float*)d_in[0];
    const float* W = (const float*)d_in[1];
    if (in_sizes[0] != B * NN * DI) {     // defensive input-order check
        x = (const float*)d_in[1];
        W = (const float*)d_in[0];
    }
    float* out = (float*)d_out;

    // Round 0: GEMM + c=0.1 sum + u_hat fp16 store
    pass0_kernel<<<NBLK, 128>>>(x, W);
    reduce1_kernel<<<B * NSLICE, 160>>>();
    squash_kernel<<<B, 160>>>(out, 0.1f, 0);
    // Round 1: logits vs v0
    routed_kernel<<<8 * RNB, 128>>>();
    squash_kernel<<<B, 160>>>(out, 1.0f, 1);
    // Round 2: logits vs v0+v1, final output
    routed_kernel<<<8 * RNB, 128>>>();
    squash_kernel<<<B, 160>>>(out, 1.0f, 2);
}